// round 9
// baseline (speedup 1.0000x reference)
#include <cuda_runtime.h>
#include <math.h>

#define NN    4096
#define NI_   1024
#define NB    8
#define NT    500
#define NWORD 128          // NN/32
#define SIM_CTAS 128       // 8 batches x 16 col-blocks (256 cols each)
#define SIM_TPB  512       // 256 E threads + 256 I threads, 1 col/thread

// ---- device scratch ----
__device__ float     g_weff[(size_t)NN * NN];          // 64 MB
__device__ float     g_dff[(size_t)NT * NB * NN];      // 65.5 MB [t][b*N+j]
__device__ unsigned  g_mask[2][2][NB][NWORD];          // [buf][type][batch][word]
__device__ unsigned  g_cntB[NB * 32];                  // per-batch barrier counters (padded)

struct SimConsts {
    float ar[4], ad[4], omad[4], esyn[4];
    float dtt0, dtt1;
};

// ------------------------------------------------------------------
__global__ void init_kernel() {
    int idx = blockIdx.x * blockDim.x + threadIdx.x;
    if (idx < NB * 32) g_cntB[idx] = 0u;
    if (idx < 2 * NB * NWORD) ((unsigned*)g_mask[0])[idx] = 0u;
}

// ------------------------------------------------------------------
__global__ void weff_kernel(const float* __restrict__ W,
                            const float* __restrict__ scal,
                            const int*   __restrict__ ci) {
    int idx = blockIdx.x * 256 + threadIdx.x;          // float4 index
    int e = idx << 2;
    int i = e >> 12;
    int j = e & (NN - 1);
    float4 w = __ldg((const float4*)W + idx);
    int cri = __ldg(&ci[i]) * 2;
    float4 r;
    r.x = __fmul_rn(w.x, __ldg(&scal[cri + __ldg(&ci[j + 0])]));
    r.y = __fmul_rn(w.y, __ldg(&scal[cri + __ldg(&ci[j + 1])]));
    r.z = __fmul_rn(w.z, __ldg(&scal[cri + __ldg(&ci[j + 2])]));
    r.w = __fmul_rn(w.w, __ldg(&scal[cri + __ldg(&ci[j + 3])]));
    ((float4*)g_weff)[idx] = r;
}

// ------------------------------------------------------------------
// FF drive: active-row compaction + float4 row loads (unchanged).
// ------------------------------------------------------------------
__global__ void ff_kernel(const float* __restrict__ sp,
                          const float* __restrict__ wff,
                          const float* __restrict__ sff,
                          const int*   __restrict__ ciff,
                          const int*   __restrict__ ci) {
    __shared__ int    s_act[NI_];
    __shared__ float2 s_fv[NI_];
    __shared__ int    s_cnt[33];

    const int x   = blockIdx.x;
    const int t   = x >> 3;
    const int b   = x & 7;
    const int tid = threadIdx.x;
    const int lane = tid & 31;
    const int wrp  = tid >> 5;

    bool act[4]; int rnk[4];
#pragma unroll
    for (int r = 0; r < 4; ++r) {
        int i = r * 256 + tid;
        float sv = __ldg(&sp[((size_t)b * NT + t) * NI_ + i]);
        bool a = (sv != 0.0f);
        unsigned bal = __ballot_sync(0xffffffffu, a);
        if (lane == 0) s_cnt[r * 8 + wrp] = __popc(bal);
        act[r] = a;
        rnk[r] = __popc(bal & ((1u << lane) - 1u));
    }
    __syncthreads();
    if (tid == 0) {
        int run = 0;
#pragma unroll
        for (int s = 0; s < 32; ++s) { int c = s_cnt[s]; s_cnt[s] = run; run += c; }
        s_cnt[32] = run;
    }
    __syncthreads();
#pragma unroll
    for (int r = 0; r < 4; ++r) {
        if (act[r]) {
            int i = r * 256 + tid;
            int pos = s_cnt[r * 8 + wrp] + rnk[r];
            s_act[pos] = i << 10;
            int cf = __ldg(&ciff[i]) * 2;
            s_fv[pos] = make_float2(__ldg(&sff[cf]), __ldg(&sff[cf + 1]));
        }
    }
    __syncthreads();
    const int total = s_cnt[32];

    int4 ctq[4];
#pragma unroll
    for (int r = 0; r < 4; ++r) ctq[r] = __ldg((const int4*)ci + tid + 256 * r);

    float4 acc[4];
#pragma unroll
    for (int r = 0; r < 4; ++r) acc[r] = make_float4(0, 0, 0, 0);

    for (int k = 0; k < total; ++k) {
        int roff = s_act[k];
        float2 f = s_fv[k];
#pragma unroll
        for (int r = 0; r < 4; ++r) {
            float4 w4 = __ldg((const float4*)wff + roff + tid + 256 * r);
            acc[r].x = __fadd_rn(acc[r].x, __fmul_rn(w4.x, ctq[r].x ? f.y : f.x));
            acc[r].y = __fadd_rn(acc[r].y, __fmul_rn(w4.y, ctq[r].y ? f.y : f.x));
            acc[r].z = __fadd_rn(acc[r].z, __fmul_rn(w4.z, ctq[r].z ? f.y : f.x));
            acc[r].w = __fadd_rn(acc[r].w, __fmul_rn(w4.w, ctq[r].w ? f.y : f.x));
        }
    }
    size_t o = (size_t)x * (NN / 4);
#pragma unroll
    for (int r = 0; r < 4; ++r) ((float4*)g_dff)[o + tid + 256 * r] = acc[r];
}

// ------------------------------------------------------------------
// Persistent sim: 512 threads/CTA (16 warps/SM), 1 column per thread,
// scalar depth-16 double-buffer gather, ballot-direct mask publish.
// ------------------------------------------------------------------
__global__ void __launch_bounds__(SIM_TPB, 1)
sim_kernel(const int* __restrict__ ci, float* __restrict__ out, SimConsts C) {
    __shared__ int   s_lstE[NN];
    __shared__ int   s_lstI[NN];
    __shared__ float s_accI[256];
    __shared__ int   s_wsum[4];

    const int tid  = threadIdx.x;
    const int lane = tid & 31;
    const int wrp  = tid >> 5;
    const bool isE = (tid < 256);
    const int c    = tid & 255;                    // column within block
    const int b    = blockIdx.x >> 4;
    const int jb   = (blockIdx.x & 15) << 8;
    const int j    = jb + c;
    const int myct = __ldg(&ci[j]);

    // list-builder role (warps 0-3 only)
    const int type = wrp >> 1;
    const int half = wrp & 1;

    const float dtt   = myct ? C.dtt1 : C.dtt0;
    const float refst = myct ? 10.0f : 20.0f;
    const float theta = -50.0f, u_reset = -65.0f, e_l = -70.0f, g_l = 10.0f;

    float v = e_l, ref = 0.0f;
    float h0 = 0, h1 = 0, h2 = 0, h3 = 0;
    float q0 = 0, q1 = 0, q2 = 0, q3 = 0;

    const float* __restrict__ Wcol = g_weff + j;
    float* outp = out + ((size_t)b * NT) * NN + j;
    const float* dffp = g_dff + (size_t)b * NN + j;
    unsigned* cntp = &g_cntB[b * 32];

    float dff_cur = 0.0f, dff_next = 0.0f;
    if (isE) dff_cur = __ldg(dffp);

    for (int t = 0; t < NT; ++t) {
        const int p = t & 1;

        // ---- 1. masks -> ascending compact lists (warps 0-3) ----
        if (wrp < 4) {
            unsigned w0 = __ldcg(&g_mask[p][type][b][half * 64 + lane]);
            unsigned w1 = __ldcg(&g_mask[p][type][b][half * 64 + 32 + lane]);
            int c0 = __popc(w0), c1 = __popc(w1);
            int s0 = c0, s1 = c1;
#pragma unroll
            for (int d = 1; d < 32; d <<= 1) {
                int t0 = __shfl_up_sync(0xffffffffu, s0, d);
                int t1 = __shfl_up_sync(0xffffffffu, s1, d);
                if (lane >= d) { s0 += t0; s1 += t1; }
            }
            int tot0    = __shfl_sync(0xffffffffu, s0, 31);
            int tothalf = tot0 + __shfl_sync(0xffffffffu, s1, 31);
            if (lane == 31) s_wsum[wrp] = tothalf;
            __syncthreads();
            {
                int base_half = half ? s_wsum[type * 2] : 0;
                int* dst = type ? s_lstI : s_lstE;
                int pos = base_half + s0 - c0;
                int ib  = (half * 64 + lane) << 5;
                unsigned m = w0;
                while (m) {
                    int bit = __ffs(m) - 1; m &= m - 1;
                    dst[pos++] = (ib + bit) << 12;      // i * 4096 (float stride)
                }
                pos = base_half + tot0 + s1 - c1;
                ib  = (half * 64 + 32 + lane) << 5;
                m = w1;
                while (m) {
                    int bit = __ffs(m) - 1; m &= m - 1;
                    dst[pos++] = (ib + bit) << 12;
                }
            }
        } else {
            __syncthreads();
        }
        __syncthreads();
        const int totE = s_wsum[0] + s_wsum[1];
        const int totI = s_wsum[2] + s_wsum[3];

        if (isE && t + 1 < NT)
            dff_next = __ldg(dffp + (size_t)(t + 1) * (NB * NN));

        // ---- 2. scalar gather, depth-16 double buffer ----
        const int  tot = isE ? totE : totI;
        const int* lst = isE ? s_lstE : s_lstI;
        float acc = 0.0f;
        {
            float bA[16], bB[16];
#pragma unroll
            for (int u = 0; u < 16; ++u)
                bA[u] = (u < tot) ? __ldg(Wcol + lst[u]) : 0.0f;
            for (int base = 0; base < tot; base += 32) {
#pragma unroll
                for (int u = 0; u < 16; ++u) {
                    int k = base + 16 + u;
                    bB[u] = (k < tot) ? __ldg(Wcol + lst[k]) : 0.0f;
                }
#pragma unroll
                for (int u = 0; u < 16; ++u) acc = __fadd_rn(acc, bA[u]);
#pragma unroll
                for (int u = 0; u < 16; ++u) {
                    int k = base + 32 + u;
                    bA[u] = (k < tot) ? __ldg(Wcol + lst[k]) : 0.0f;
                }
#pragma unroll
                for (int u = 0; u < 16; ++u) acc = __fadd_rn(acc, bB[u]);
            }
        }
        if (!isE) s_accI[c] = acc;
        __syncthreads();

        // ---- 3. membrane update + ballot-direct publish (E threads) ----
        if (isE) {
            float acc_e = acc;
            float acc_i = s_accI[c];
            h0 = __fmaf_rn(h0, C.ar[0], acc_e);
            h1 = __fmaf_rn(h1, C.ar[1], __fmul_rn(acc_e, 0.5f));
            h2 = __fmaf_rn(h2, C.ar[2], acc_i);
            h3 = __fmaf_rn(h3, C.ar[3], dff_cur);
            q0 = __fmaf_rn(q0, C.ad[0], __fmul_rn(C.omad[0], h0));
            q1 = __fmaf_rn(q1, C.ad[1], __fmul_rn(C.omad[1], h1));
            q2 = __fmaf_rn(q2, C.ad[2], __fmul_rn(C.omad[2], h2));
            q3 = __fmaf_rn(q3, C.ad[3], __fmul_rn(C.omad[3], h3));

            float I = __fmul_rn(q0, __fsub_rn(C.esyn[0], v));
            I = __fadd_rn(I, __fmul_rn(q1, __fsub_rn(C.esyn[1], v)));
            I = __fadd_rn(I, __fmul_rn(q2, __fsub_rn(C.esyn[2], v)));
            I = __fadd_rn(I, __fmul_rn(q3, __fsub_rn(C.esyn[3], v)));

            float vn = __fmaf_rn(dtt,
                                 __fadd_rn(__fsub_rn(e_l, v), __fdiv_rn(I, g_l)),
                                 v);
            bool refr = (ref > 0.0f);
            if (refr) vn = u_reset;
            bool  spk = (!refr) && (vn > theta);
            float sn  = spk ? 1.0f : 0.0f;
            v   = spk ? u_reset : vn;
            ref = spk ? refst : fmaxf(__fsub_rn(ref, 1.0f), 0.0f);
            outp[(size_t)t * NN] = sn;

            unsigned be = __ballot_sync(0xffffffffu, spk && (myct == 0));
            unsigned bi = __ballot_sync(0xffffffffu, spk && (myct == 1));
            if (t != NT - 1 && lane == 0) {
                const int qb   = p ^ 1;
                const int word = (jb >> 5) + wrp;      // E warps 0-7 -> 8 words
                g_mask[qb][0][b][word] = be;
                g_mask[qb][1][b][word] = bi;
                // release orders this warp's two mask stores; 8 arrivals/CTA
                asm volatile("red.release.gpu.global.add.u32 [%0], %1;"
                             :: "l"(cntp), "r"(1u) : "memory");
            }
        }
        dff_cur = dff_next;

        // ---- 4. per-warp barrier poll (128 arrivals per batch per step) ----
        if (t != NT - 1) {
            const unsigned target = 128u * (unsigned)(t + 1);
            if (lane == 0) {
                unsigned cv;
                do {
                    asm volatile("ld.acquire.gpu.global.u32 %0, [%1];"
                                 : "=r"(cv) : "l"(cntp));
                } while (cv < target);
            }
            __syncwarp();
        }
    }
}

// ------------------------------------------------------------------
extern "C" void kernel_launch(void* const* d_in, const int* in_sizes, int n_in,
                              void* d_out, int out_size) {
    const float* in_spikes = (const float*)d_in[0];
    const float* weights   = (const float*)d_in[1];
    const float* wff       = (const float*)d_in[2];
    const float* scal      = (const float*)d_in[3];
    const float* scalff    = (const float*)d_in[4];
    const int*   ci        = (const int*)  d_in[5];
    const int*   ciff      = (const int*)  d_in[6];
    float*       out       = (float*)d_out;

    const float tau_rise[4]  = {0.5f, 2.0f, 0.5f, 0.5f};
    const float tau_decay[4] = {2.0f, 100.0f, 5.0f, 2.0f};
    SimConsts C;
    for (int s = 0; s < 4; ++s) {
        float qr = -(0.1f / tau_rise[s]);
        float qd = -(0.1f / tau_decay[s]);
        C.ar[s]   = (float)exp((double)qr);
        C.ad[s]   = (float)exp((double)qd);
        C.omad[s] = 1.0f - C.ad[s];
    }
    C.esyn[0] = 0.0f; C.esyn[1] = 0.0f; C.esyn[2] = -80.0f; C.esyn[3] = 0.0f;
    C.dtt0 = 0.1f / 20.0f;
    C.dtt1 = 0.1f / 10.0f;

    init_kernel<<<8, 256>>>();
    weff_kernel<<<(NN * NN / 4) / 256, 256>>>(weights, scal, ci);
    ff_kernel<<<NT * NB, 256>>>(in_spikes, wff, scalff, ciff, ci);
    sim_kernel<<<SIM_CTAS, SIM_TPB>>>(ci, out, C);
}